// round 1
// baseline (speedup 1.0000x reference)
#include <cuda_runtime.h>
#include <math.h>

// Problem shapes (fixed by the reference)
#define BATCH      16384
#define N_FEATURES 128
#define HIDDEN     64

#define WARPS_PER_BLOCK 8
#define THREADS (WARPS_PER_BLOCK * 32)

// exact GELU: 0.5*x*(1+erf(x/sqrt(2)))
__device__ __forceinline__ float gelu_exact(float v) {
    return 0.5f * v * (1.0f + erff(v * 0.70710678118654752f));
}

__global__ __launch_bounds__(THREADS)
void hypernet_kernel(const float* __restrict__ x,
                     const int*   __restrict__ task_ids,
                     const float* __restrict__ l1_emb,   // [NUM_TASKS, 128*64]
                     const float* __restrict__ l1_bias,  // [NUM_TASKS, 64]
                     const float* __restrict__ l2_emb,   // [NUM_TASKS, 64]
                     const float* __restrict__ l2_bias,  // [NUM_TASKS, 1]
                     float*       __restrict__ out)      // [BATCH, 1]
{
    __shared__ float xs[WARPS_PER_BLOCK][N_FEATURES];

    const int warp  = threadIdx.x >> 5;
    const int lane  = threadIdx.x & 31;
    const int sample = blockIdx.x * WARPS_PER_BLOCK + warp;
    if (sample >= BATCH) return;

    // Stage this sample's x into shared (warp-local, float4, fully coalesced)
    {
        const float4* xg = reinterpret_cast<const float4*>(x + (size_t)sample * N_FEATURES);
        float4 v = xg[lane];                 // 32 lanes * 4 = 128 floats
        float4* xsv = reinterpret_cast<float4*>(xs[warp]);
        xsv[lane] = v;
    }
    __syncwarp();

    const int task = task_ids[sample];
    const float* w1 = l1_emb + (size_t)task * (N_FEATURES * HIDDEN);

    // Lane layout: tf = lane>>4 (2-way split over F), tc = lane&15 (H via float4)
    const int tf = lane >> 4;
    const int tc = lane & 15;

    // w1 viewed as float4: row f occupies float4 indices [f*16, f*16+16)
    const float4* w1v = reinterpret_cast<const float4*>(w1) + tf * 16 + tc;

    float a0 = 0.f, a1 = 0.f, a2 = 0.f, a3 = 0.f;

    // 64 iterations per thread; each warp iteration reads 2 full W1 rows (512B, coalesced)
    #pragma unroll 16
    for (int i = 0; i < N_FEATURES / 2; ++i) {
        const int f = tf + 2 * i;
        float  xv = xs[warp][f];
        float4 wv = w1v[i * 32];             // advance 2 rows = 32 float4
        a0 = fmaf(xv, wv.x, a0);
        a1 = fmaf(xv, wv.y, a1);
        a2 = fmaf(xv, wv.z, a2);
        a3 = fmaf(xv, wv.w, a3);
    }

    // Fold the 2-way F split (lanes tc and tc+16 end up with the full sums)
    a0 += __shfl_xor_sync(0xffffffffu, a0, 16);
    a1 += __shfl_xor_sync(0xffffffffu, a1, 16);
    a2 += __shfl_xor_sync(0xffffffffu, a2, 16);
    a3 += __shfl_xor_sync(0xffffffffu, a3, 16);

    // bias + GELU + dot with w2
    const float4 b1 = reinterpret_cast<const float4*>(l1_bias + (size_t)task * HIDDEN)[tc];
    const float4 w2 = reinterpret_cast<const float4*>(l2_emb  + (size_t)task * HIDDEN)[tc];

    float h0 = gelu_exact(a0 + b1.x);
    float h1 = gelu_exact(a1 + b1.y);
    float h2 = gelu_exact(a2 + b1.z);
    float h3 = gelu_exact(a3 + b1.w);

    float dot = fmaf(h0, w2.x, fmaf(h1, w2.y, fmaf(h2, w2.z, h3 * w2.w)));

    // Butterfly over the 16-lane group: lane 0 (and 16) get the group sum.
    // Both tf halves hold identical h, so each 16-group independently sums 16*4=64 terms.
    dot += __shfl_xor_sync(0xffffffffu, dot, 8);
    dot += __shfl_xor_sync(0xffffffffu, dot, 4);
    dot += __shfl_xor_sync(0xffffffffu, dot, 2);
    dot += __shfl_xor_sync(0xffffffffu, dot, 1);

    if (lane == 0) {
        out[sample] = dot + __ldg(l2_bias + task);
    }
}

extern "C" void kernel_launch(void* const* d_in, const int* in_sizes, int n_in,
                              void* d_out, int out_size) {
    const float* x       = (const float*)d_in[0];
    const int*   taskids = (const int*)  d_in[1];
    const float* l1_emb  = (const float*)d_in[2];
    const float* l1_bias = (const float*)d_in[3];
    const float* l2_emb  = (const float*)d_in[4];
    const float* l2_bias = (const float*)d_in[5];
    float* out = (float*)d_out;

    const int blocks = BATCH / WARPS_PER_BLOCK;   // 2048
    hypernet_kernel<<<blocks, THREADS>>>(x, taskids, l1_emb, l1_bias,
                                         l2_emb, l2_bias, out);
}